// round 2
// baseline (speedup 1.0000x reference)
#include <cuda_runtime.h>
#include <math.h>

// Problem constants
#define BSZ   128
#define TLEN  200
#define NNODE 512
#define EDIM  64
#define LLAG  30
#define TP    170          // TLEN - LLAG
#define WARPS 8            // warps per block, one target-t per warp

__device__ __forceinline__ float leaky(float x) { return x >= 0.f ? x : 0.01f * x; }

struct Smem {
    float W0bT[64][64];   // W0bT[j][i] = iv_W0[(64+i)*64 + j]  (hist half, transposed)
    float W1T [64][64];   // W1T[j][i]  = iv_W1[i*64 + j]
    float WfT [64][64];   // WfT[j][i]  = iv_Wf[i*64 + j]
    float FoW0[64][64];   // natural [i][j]
    float FoW1[64][64];   // natural [i][j]
    float FoWf[64][2];    // natural [i][o]
    float ivB0v[64], ivG1v[64], ivBe1v[64], ivB1v[64], ivGfv[64], ivBefv[64], ivBfv[64];
    float foB0v[64], foG1v[64], foBe1v[64], foB1v[64], foGfv[64], foBefv[64];
    float foBfv[2];
    float c_s   [WARPS][64];   // per-warp target contribution (b0 + emb_tgt @ W0_top)
    float lnbuf [WARPS][64];   // per-warp LN exchange buffer (fo MLP)
    float cross_s[WARPS][64];  // per-warp cross_effect vector
};

__global__ __launch_bounds__(256, 1)
void gtm_kernel(const int*   __restrict__ skill,
                const int*   __restrict__ timeq,
                const int*   __restrict__ label,
                const float* __restrict__ adj,
                const float* __restrict__ nemb,
                const float* __restrict__ ivW0, const float* __restrict__ ivB0,
                const float* __restrict__ ivG1, const float* __restrict__ ivBe1,
                const float* __restrict__ ivW1, const float* __restrict__ ivB1,
                const float* __restrict__ ivGf, const float* __restrict__ ivBef,
                const float* __restrict__ ivWf, const float* __restrict__ ivBf,
                const float* __restrict__ foW0, const float* __restrict__ foB0,
                const float* __restrict__ foG1, const float* __restrict__ foBe1,
                const float* __restrict__ foW1, const float* __restrict__ foB1,
                const float* __restrict__ foGf, const float* __restrict__ foBef,
                const float* __restrict__ foWf, const float* __restrict__ foBf,
                float* __restrict__ out)
{
    extern __shared__ char smem_raw[];
    Smem& s = *reinterpret_cast<Smem*>(smem_raw);

    const int tid = threadIdx.x;

    // ---- stage weights into shared memory (transposing the iv mats) ----
    for (int idx = tid; idx < 4096; idx += 256) {
        int j = idx >> 6, i = idx & 63;
        s.W0bT[j][i] = ivW0[(64 + i) * 64 + j];
        s.W1T [j][i] = ivW1[i * 64 + j];
        s.WfT [j][i] = ivWf[i * 64 + j];
        (&s.FoW0[0][0])[idx] = foW0[idx];
        (&s.FoW1[0][0])[idx] = foW1[idx];
    }
    if (tid < 64) {
        s.ivB0v [tid] = ivB0 [tid];
        s.ivG1v [tid] = ivG1 [tid];
        s.ivBe1v[tid] = ivBe1[tid];
        s.ivB1v [tid] = ivB1 [tid];
        s.ivGfv [tid] = ivGf [tid];
        s.ivBefv[tid] = ivBef[tid];
        s.ivBfv [tid] = ivBf [tid];
        s.foB0v [tid] = foB0 [tid];
        s.foG1v [tid] = foG1 [tid];
        s.foBe1v[tid] = foBe1[tid];
        s.foB1v [tid] = foB1 [tid];
        s.foGfv [tid] = foGf [tid];
        s.foBefv[tid] = foBef[tid];
    }
    if (tid < 128) (&s.FoWf[0][0])[tid] = foWf[tid];
    if (tid < 2)   s.foBfv[tid] = foBf[tid];
    __syncthreads();

    const int warp = tid >> 5;
    const int lane = tid & 31;
    const int tp = blockIdx.x * WARPS + warp;   // target position in [0, TP)
    if (tp >= TP) return;
    const int b = blockIdx.y;
    const int base = b * TLEN;

    // ---- per-target precompute: c[j] = b0[j] + emb_tgt . W0_top[:, j] ----
    const int   st   = skill[base + tp + LLAG];
    const float ttgt = (float)timeq[base + tp + LLAG];
    const int j0 = lane, j1 = lane + 32;
    {
        float c0 = s.ivB0v[j0], c1 = s.ivB0v[j1];
        const float* et = nemb + st * EDIM;
        #pragma unroll 8
        for (int i = 0; i < 64; i++) {
            float e = et[i];                        // broadcast, L1/L2-resident
            c0 = fmaf(e, ivW0[i * 64 + j0], c0);    // coalesced 128B lines
            c1 = fmaf(e, ivW0[i * 64 + j1], c1);
        }
        s.c_s[warp][j0] = c0;
        s.c_s[warp][j1] = c1;
    }
    __syncwarp();

    // ---- per-edge setup (lane = history slot l; lanes 30,31 contribute 0) ----
    const bool el   = lane < LLAG;
    const int  hidx = base + tp + (el ? lane : 0);
    const int   sh   = skill[hidx];
    const float labf = (label[hidx] == 0) ? -1.f : 1.f;
    const float th   = (float)timeq[hidx];
    const float INV_LN5 = 0.6213349345596119f;     // 1 / ln(5)
    const float dtw = logf(fabsf(th - ttgt) + 1e-6f) * INV_LN5;
    float wgt = 0.f;
    if (el) {
        float cw = adj[((size_t)(b * NNODE + sh)) * NNODE + st];
        wgt = cw * expf(-dtw);
    }

    float A[64], B[64];
    {
        const float4* nr = reinterpret_cast<const float4*>(nemb + sh * EDIM);
        #pragma unroll
        for (int k = 0; k < 16; k++) {
            float4 v = nr[k];
            A[4*k+0] = v.x * labf; A[4*k+1] = v.y * labf;
            A[4*k+2] = v.z * labf; A[4*k+3] = v.w * labf;
        }
    }

    // ---- iv stage 1: B = leaky(c + emb_hist @ W0_bot) ----
    #pragma unroll
    for (int j = 0; j < 64; j++) {
        float a0 = 0.f, a1 = 0.f;
        const float4* wr = reinterpret_cast<const float4*>(s.W0bT[j]);  // broadcast
        #pragma unroll
        for (int k = 0; k < 16; k++) {
            float4 wv = wr[k];
            a0 = fmaf(A[4*k+0], wv.x, a0);
            a1 = fmaf(A[4*k+1], wv.y, a1);
            a0 = fmaf(A[4*k+2], wv.z, a0);
            a1 = fmaf(A[4*k+3], wv.w, a1);
        }
        B[j] = leaky(s.c_s[warp][j] + a0 + a1);
    }

    // ---- LN1 (per-lane, in registers) -> A ----
    {
        float m = 0.f;
        #pragma unroll
        for (int j = 0; j < 64; j++) m += B[j];
        m *= (1.f / 64.f);
        float v = 0.f;
        #pragma unroll
        for (int j = 0; j < 64; j++) { float d = B[j] - m; v = fmaf(d, d, v); }
        float rs = rsqrtf(v * (1.f / 64.f) + 1e-5f);
        #pragma unroll
        for (int j = 0; j < 64; j++)
            A[j] = fmaf((B[j] - m) * rs, s.ivG1v[j], s.ivBe1v[j]);
    }

    // ---- iv stage 2: B += leaky(A @ W1 + b1) ----
    #pragma unroll
    for (int j = 0; j < 64; j++) {
        float a0 = 0.f, a1 = 0.f;
        const float4* wr = reinterpret_cast<const float4*>(s.W1T[j]);
        #pragma unroll
        for (int k = 0; k < 16; k++) {
            float4 wv = wr[k];
            a0 = fmaf(A[4*k+0], wv.x, a0);
            a1 = fmaf(A[4*k+1], wv.y, a1);
            a0 = fmaf(A[4*k+2], wv.z, a0);
            a1 = fmaf(A[4*k+3], wv.w, a1);
        }
        B[j] += leaky(s.ivB1v[j] + a0 + a1);
    }

    // ---- LN-final -> A ----
    {
        float m = 0.f;
        #pragma unroll
        for (int j = 0; j < 64; j++) m += B[j];
        m *= (1.f / 64.f);
        float v = 0.f;
        #pragma unroll
        for (int j = 0; j < 64; j++) { float d = B[j] - m; v = fmaf(d, d, v); }
        float rs = rsqrtf(v * (1.f / 64.f) + 1e-5f);
        #pragma unroll
        for (int j = 0; j < 64; j++)
            A[j] = fmaf((B[j] - m) * rs, s.ivGfv[j], s.ivBefv[j]);
    }

    // ---- iv stage 3 (msg = A @ Wf + bf) fused with einsum reduction ----
    #pragma unroll
    for (int j = 0; j < 64; j++) {
        float a0 = 0.f, a1 = 0.f;
        const float4* wr = reinterpret_cast<const float4*>(s.WfT[j]);
        #pragma unroll
        for (int k = 0; k < 16; k++) {
            float4 wv = wr[k];
            a0 = fmaf(A[4*k+0], wv.x, a0);
            a1 = fmaf(A[4*k+1], wv.y, a1);
            a0 = fmaf(A[4*k+2], wv.z, a0);
            a1 = fmaf(A[4*k+3], wv.w, a1);
        }
        float v = wgt * (s.ivBfv[j] + a0 + a1);     // wgt == 0 on idle lanes
        #pragma unroll
        for (int off = 16; off; off >>= 1)
            v += __shfl_xor_sync(0xffffffffu, v, off);
        if (lane == 0) s.cross_s[warp][j] = v;
    }
    __syncwarp();

    // ---- fo MLP on cross_effect (warp-cooperative, lane owns j0,j1) ----
    float x0 = s.cross_s[warp][j0];
    float x1 = s.cross_s[warp][j1];
    float a0 = s.foB0v[j0], a1 = s.foB0v[j1];
    #pragma unroll 8
    for (int i = 0; i < 64; i++) {
        float xi = s.cross_s[warp][i];
        a0 = fmaf(xi, s.FoW0[i][j0], a0);
        a1 = fmaf(xi, s.FoW0[i][j1], a1);
    }
    float h0 = x0 + leaky(a0);
    float h1 = x1 + leaky(a1);

    // LN across warp (64 values, 2 per lane)
    float sm = h0 + h1;
    #pragma unroll
    for (int off = 16; off; off >>= 1) sm += __shfl_xor_sync(0xffffffffu, sm, off);
    float m = sm * (1.f / 64.f);
    float d0 = h0 - m, d1 = h1 - m;
    float vv = fmaf(d0, d0, d1 * d1);
    #pragma unroll
    for (int off = 16; off; off >>= 1) vv += __shfl_xor_sync(0xffffffffu, vv, off);
    float rs = rsqrtf(vv * (1.f / 64.f) + 1e-5f);
    float l0 = fmaf(d0 * rs, s.foG1v[j0], s.foBe1v[j0]);
    float l1 = fmaf(d1 * rs, s.foG1v[j1], s.foBe1v[j1]);
    s.lnbuf[warp][j0] = l0;
    s.lnbuf[warp][j1] = l1;
    __syncwarp();

    a0 = s.foB1v[j0]; a1 = s.foB1v[j1];
    #pragma unroll 8
    for (int i = 0; i < 64; i++) {
        float xi = s.lnbuf[warp][i];
        a0 = fmaf(xi, s.FoW1[i][j0], a0);
        a1 = fmaf(xi, s.FoW1[i][j1], a1);
    }
    h0 += leaky(a0);
    h1 += leaky(a1);

    // LN final
    sm = h0 + h1;
    #pragma unroll
    for (int off = 16; off; off >>= 1) sm += __shfl_xor_sync(0xffffffffu, sm, off);
    m = sm * (1.f / 64.f);
    d0 = h0 - m; d1 = h1 - m;
    vv = fmaf(d0, d0, d1 * d1);
    #pragma unroll
    for (int off = 16; off; off >>= 1) vv += __shfl_xor_sync(0xffffffffu, vv, off);
    rs = rsqrtf(vv * (1.f / 64.f) + 1e-5f);
    l0 = fmaf(d0 * rs, s.foGfv[j0], s.foBefv[j0]);
    l1 = fmaf(d1 * rs, s.foGfv[j1], s.foBefv[j1]);

    // logits (out_dim=2) and softmax[..., 1]
    float p0 = fmaf(l0, s.FoWf[j0][0], l1 * s.FoWf[j1][0]);
    float p1 = fmaf(l0, s.FoWf[j0][1], l1 * s.FoWf[j1][1]);
    #pragma unroll
    for (int off = 16; off; off >>= 1) {
        p0 += __shfl_xor_sync(0xffffffffu, p0, off);
        p1 += __shfl_xor_sync(0xffffffffu, p1, off);
    }
    if (lane == 0) {
        float lg0 = p0 + s.foBfv[0];
        float lg1 = p1 + s.foBfv[1];
        float mx = fmaxf(lg0, lg1);
        float e0 = expf(lg0 - mx);
        float e1 = expf(lg1 - mx);
        out[b * TP + tp] = e1 / (e0 + e1);
    }
}

extern "C" void kernel_launch(void* const* d_in, const int* in_sizes, int n_in,
                              void* d_out, int out_size)
{
    (void)in_sizes; (void)n_in; (void)out_size;
    const int*   skill = (const int*)  d_in[0];
    const int*   timeq = (const int*)  d_in[2];
    const int*   label = (const int*)  d_in[3];
    const float* adj   = (const float*)d_in[4];
    const float* nemb  = (const float*)d_in[5];
    const float* ivW0  = (const float*)d_in[6];
    const float* ivB0  = (const float*)d_in[7];
    const float* ivG1  = (const float*)d_in[8];
    const float* ivBe1 = (const float*)d_in[9];
    const float* ivW1  = (const float*)d_in[10];
    const float* ivB1  = (const float*)d_in[11];
    const float* ivGf  = (const float*)d_in[12];
    const float* ivBef = (const float*)d_in[13];
    const float* ivWf  = (const float*)d_in[14];
    const float* ivBf  = (const float*)d_in[15];
    const float* foW0  = (const float*)d_in[16];
    const float* foB0  = (const float*)d_in[17];
    const float* foG1  = (const float*)d_in[18];
    const float* foBe1 = (const float*)d_in[19];
    const float* foW1  = (const float*)d_in[20];
    const float* foB1  = (const float*)d_in[21];
    const float* foGf  = (const float*)d_in[22];
    const float* foBef = (const float*)d_in[23];
    const float* foWf  = (const float*)d_in[24];
    const float* foBf  = (const float*)d_in[25];

    cudaFuncSetAttribute(gtm_kernel, cudaFuncAttributeMaxDynamicSharedMemorySize,
                         (int)sizeof(Smem));

    dim3 grid((TP + WARPS - 1) / WARPS, BSZ);
    gtm_kernel<<<grid, 256, sizeof(Smem)>>>(
        skill, timeq, label, adj, nemb,
        ivW0, ivB0, ivG1, ivBe1, ivW1, ivB1, ivGf, ivBef, ivWf, ivBf,
        foW0, foB0, foG1, foBe1, foW1, foB1, foGf, foBef, foWf, foBf,
        (float*)d_out);
}

// round 4
// speedup vs baseline: 1.3528x; 1.3528x over previous
#include <cuda_runtime.h>
#include <math.h>

// Problem constants
#define BSZ   128
#define TLEN  200
#define NNODE 512
#define EDIM  64
#define LLAG  30
#define TP    170          // TLEN - LLAG
#define WARPS 8            // warps per block, one target-t per warp
#define NPOS  38           // positions staged per block: WARPS-1 + LLAG + 1 + ... = 8+30
#define EPAD  68           // padded row length (floats) for conflict-free LDS

typedef unsigned long long ull;

__device__ __forceinline__ float leaky(float x) { return x >= 0.f ? x : 0.01f * x; }

__device__ __forceinline__ ull pk2(float lo, float hi) {
    ull r; asm("mov.b64 %0, {%1, %2};" : "=l"(r) : "f"(lo), "f"(hi)); return r;
}
__device__ __forceinline__ void upk2(float& lo, float& hi, ull v) {
    asm("mov.b64 {%0, %1}, %2;" : "=f"(lo), "=f"(hi) : "l"(v));
}
__device__ __forceinline__ ull fma2(ull a, ull b, ull c) {
    ull d; asm("fma.rn.f32x2 %0, %1, %2, %3;" : "=l"(d) : "l"(a), "l"(b), "l"(c)); return d;
}

struct Smem {
    float W0bT[64][64];   // W0bT[j][i] = iv_W0[(64+i)*64 + j]  (hist half, transposed; pairs along i)
    float W1T [64][64];   // W1T[j][i]  = iv_W1[i*64 + j]
    float WfT [64][64];   // WfT[j][i]  = iv_Wf[i*64 + j]
    float W0tN[64][64];   // natural [i][j] = iv_W0[i*64+j]  (target half)
    float FoW0[64][64];   // natural [i][j]
    float FoW1[64][64];   // natural [i][j]
    float FoWf[64][2];
    float epos[NPOS][EPAD];  // staged embeddings for block's position window
    float ivB0v[64], ivG1v[64], ivBe1v[64], ivB1v[64], ivGfv[64], ivBefv[64], ivBfv[64];
    float foB0v[64], foG1v[64], foBe1v[64], foB1v[64], foGfv[64], foBefv[64];
    float foBfv[2];
    float c_s    [WARPS][64];
    float lnbuf  [WARPS][64];
    float cross_s[WARPS][64];
};

__global__ __launch_bounds__(256, 1)
void gtm_kernel(const int*   __restrict__ skill,
                const int*   __restrict__ timeq,
                const int*   __restrict__ label,
                const float* __restrict__ adj,
                const float* __restrict__ nemb,
                const float* __restrict__ ivW0, const float* __restrict__ ivB0,
                const float* __restrict__ ivG1, const float* __restrict__ ivBe1,
                const float* __restrict__ ivW1, const float* __restrict__ ivB1,
                const float* __restrict__ ivGf, const float* __restrict__ ivBef,
                const float* __restrict__ ivWf, const float* __restrict__ ivBf,
                const float* __restrict__ foW0, const float* __restrict__ foB0,
                const float* __restrict__ foG1, const float* __restrict__ foBe1,
                const float* __restrict__ foW1, const float* __restrict__ foB1,
                const float* __restrict__ foGf, const float* __restrict__ foBef,
                const float* __restrict__ foWf, const float* __restrict__ foBf,
                float* __restrict__ out)
{
    extern __shared__ char smem_raw[];
    Smem& s = *reinterpret_cast<Smem*>(smem_raw);

    const int tid = threadIdx.x;
    const int b = blockIdx.y;
    const int base = b * TLEN;
    const int tp_block = blockIdx.x * WARPS;

    // ---- stage weights into shared memory ----
    for (int idx = tid; idx < 4096; idx += 256) {
        int j = idx >> 6, i = idx & 63;
        s.W0bT[j][i] = ivW0[(64 + i) * 64 + j];
        s.W1T [j][i] = ivW1[i * 64 + j];
        s.WfT [j][i] = ivWf[i * 64 + j];
        (&s.W0tN[0][0])[idx] = ivW0[idx];
        (&s.FoW0[0][0])[idx] = foW0[idx];
        (&s.FoW1[0][0])[idx] = foW1[idx];
    }
    if (tid < 64) {
        s.ivB0v [tid] = ivB0 [tid];
        s.ivG1v [tid] = ivG1 [tid];
        s.ivBe1v[tid] = ivBe1[tid];
        s.ivB1v [tid] = ivB1 [tid];
        s.ivGfv [tid] = ivGf [tid];
        s.ivBefv[tid] = ivBef[tid];
        s.ivBfv [tid] = ivBf [tid];
        s.foB0v [tid] = foB0 [tid];
        s.foG1v [tid] = foG1 [tid];
        s.foBe1v[tid] = foBe1[tid];
        s.foB1v [tid] = foB1 [tid];
        s.foGfv [tid] = foGf [tid];
        s.foBefv[tid] = foBef[tid];
    }
    if (tid < 128) (&s.FoWf[0][0])[tid] = foWf[tid];
    if (tid < 2)   s.foBfv[tid] = foBf[tid];

    // ---- stage embeddings for this block's position window (coalesced) ----
    for (int idx = tid; idx < NPOS * 16; idx += 256) {
        int p = idx >> 4, q = idx & 15;
        int pos = tp_block + p; if (pos > TLEN - 1) pos = TLEN - 1;
        int sp = skill[base + pos];
        float4 v = reinterpret_cast<const float4*>(nemb + sp * EDIM)[q];
        *reinterpret_cast<float4*>(&s.epos[p][q * 4]) = v;
    }
    __syncthreads();

    const int warp = tid >> 5;
    const int lane = tid & 31;
    const int tp = tp_block + warp;
    if (tp >= TP) return;

    // ---- per-target precompute: c[j] = b0[j] + emb_tgt . W0_top[:, j] ----
    const int   st   = skill[base + tp + LLAG];
    const float ttgt = (float)timeq[base + tp + LLAG];
    const int j0 = lane, j1 = lane + 32;
    {
        float c0 = s.ivB0v[j0], c1 = s.ivB0v[j1];
        const float* et = &s.epos[warp + LLAG][0];   // target row (broadcast)
        #pragma unroll 8
        for (int i = 0; i < 64; i++) {
            float e = et[i];
            c0 = fmaf(e, s.W0tN[i][j0], c0);
            c1 = fmaf(e, s.W0tN[i][j1], c1);
        }
        s.c_s[warp][j0] = c0;
        s.c_s[warp][j1] = c1;
    }
    __syncwarp();

    // ---- per-edge setup (lane = history slot l) ----
    const bool el   = lane < LLAG;
    const int  l    = el ? lane : 0;
    const int  hidx = base + tp + l;
    const int   sh   = skill[hidx];
    const float labf = (label[hidx] == 0) ? -1.f : 1.f;
    const float th   = (float)timeq[hidx];
    const float INV_LN5 = 0.6213349345596119f;     // 1 / ln(5)
    const float dtw = logf(fabsf(th - ttgt) + 1e-6f) * INV_LN5;
    float wgt = 0.f;
    if (el) {
        float cw = adj[((size_t)(b * NNODE + sh)) * NNODE + st];
        wgt = cw * expf(-dtw);
    }

    ull A2[32];
    float B[64];
    {
        const float4* er = reinterpret_cast<const float4*>(&s.epos[warp + l][0]);
        #pragma unroll
        for (int k = 0; k < 16; k++) {
            float4 v = er[k];
            A2[2*k]   = pk2(v.x * labf, v.y * labf);
            A2[2*k+1] = pk2(v.z * labf, v.w * labf);
        }
    }
    const ull Z2 = pk2(0.f, 0.f);

    // ---- iv stage 1: B = leaky(c + emb_hist @ W0_bot) ----
    #pragma unroll
    for (int j = 0; j < 64; j++) {
        ull acc0 = Z2, acc1 = Z2;
        const ulonglong2* wr = reinterpret_cast<const ulonglong2*>(s.W0bT[j]);
        #pragma unroll
        for (int k = 0; k < 16; k++) {
            ulonglong2 wv = wr[k];
            acc0 = fma2(A2[2*k],   wv.x, acc0);
            acc1 = fma2(A2[2*k+1], wv.y, acc1);
        }
        float x0, x1, y0, y1;
        upk2(x0, x1, acc0); upk2(y0, y1, acc1);
        B[j] = leaky(s.c_s[warp][j] + (x0 + x1) + (y0 + y1));
    }

    // ---- LN1 (per-lane, registers) -> A2 ----
    {
        float m = 0.f;
        #pragma unroll
        for (int j = 0; j < 64; j++) m += B[j];
        m *= (1.f / 64.f);
        float v = 0.f;
        #pragma unroll
        for (int j = 0; j < 64; j++) { float d = B[j] - m; v = fmaf(d, d, v); }
        float rs = rsqrtf(v * (1.f / 64.f) + 1e-5f);
        #pragma unroll
        for (int j2 = 0; j2 < 32; j2++) {
            float alo = fmaf((B[2*j2]   - m) * rs, s.ivG1v[2*j2],   s.ivBe1v[2*j2]);
            float ahi = fmaf((B[2*j2+1] - m) * rs, s.ivG1v[2*j2+1], s.ivBe1v[2*j2+1]);
            A2[j2] = pk2(alo, ahi);
        }
    }

    // ---- iv stage 2: B += leaky(A @ W1 + b1) ----
    #pragma unroll
    for (int j = 0; j < 64; j++) {
        ull acc0 = Z2, acc1 = Z2;
        const ulonglong2* wr = reinterpret_cast<const ulonglong2*>(s.W1T[j]);
        #pragma unroll
        for (int k = 0; k < 16; k++) {
            ulonglong2 wv = wr[k];
            acc0 = fma2(A2[2*k],   wv.x, acc0);
            acc1 = fma2(A2[2*k+1], wv.y, acc1);
        }
        float x0, x1, y0, y1;
        upk2(x0, x1, acc0); upk2(y0, y1, acc1);
        B[j] += leaky(s.ivB1v[j] + (x0 + x1) + (y0 + y1));
    }

    // ---- LN-final -> A2 ----
    {
        float m = 0.f;
        #pragma unroll
        for (int j = 0; j < 64; j++) m += B[j];
        m *= (1.f / 64.f);
        float v = 0.f;
        #pragma unroll
        for (int j = 0; j < 64; j++) { float d = B[j] - m; v = fmaf(d, d, v); }
        float rs = rsqrtf(v * (1.f / 64.f) + 1e-5f);
        #pragma unroll
        for (int j2 = 0; j2 < 32; j2++) {
            float alo = fmaf((B[2*j2]   - m) * rs, s.ivGfv[2*j2],   s.ivBefv[2*j2]);
            float ahi = fmaf((B[2*j2+1] - m) * rs, s.ivGfv[2*j2+1], s.ivBefv[2*j2+1]);
            A2[j2] = pk2(alo, ahi);
        }
    }

    // ---- iv stage 3 (msg = A @ Wf + bf) fused with einsum reduction ----
    #pragma unroll
    for (int j = 0; j < 64; j++) {
        ull acc0 = Z2, acc1 = Z2;
        const ulonglong2* wr = reinterpret_cast<const ulonglong2*>(s.WfT[j]);
        #pragma unroll
        for (int k = 0; k < 16; k++) {
            ulonglong2 wv = wr[k];
            acc0 = fma2(A2[2*k],   wv.x, acc0);
            acc1 = fma2(A2[2*k+1], wv.y, acc1);
        }
        float x0, x1, y0, y1;
        upk2(x0, x1, acc0); upk2(y0, y1, acc1);
        float v = wgt * (s.ivBfv[j] + (x0 + x1) + (y0 + y1));  // wgt==0 on idle lanes
        #pragma unroll
        for (int off = 16; off; off >>= 1)
            v += __shfl_xor_sync(0xffffffffu, v, off);
        if (lane == 0) s.cross_s[warp][j] = v;
    }
    __syncwarp();

    // ---- fo MLP on cross_effect (warp-cooperative, lane owns j0,j1) ----
    float x0 = s.cross_s[warp][j0];
    float x1 = s.cross_s[warp][j1];
    float a0 = s.foB0v[j0], a1 = s.foB0v[j1];
    #pragma unroll 8
    for (int i = 0; i < 64; i++) {
        float xi = s.cross_s[warp][i];
        a0 = fmaf(xi, s.FoW0[i][j0], a0);
        a1 = fmaf(xi, s.FoW0[i][j1], a1);
    }
    float h0 = x0 + leaky(a0);
    float h1 = x1 + leaky(a1);

    float sm = h0 + h1;
    #pragma unroll
    for (int off = 16; off; off >>= 1) sm += __shfl_xor_sync(0xffffffffu, sm, off);
    float m = sm * (1.f / 64.f);
    float d0 = h0 - m, d1 = h1 - m;
    float vv = fmaf(d0, d0, d1 * d1);
    #pragma unroll
    for (int off = 16; off; off >>= 1) vv += __shfl_xor_sync(0xffffffffu, vv, off);
    float rs = rsqrtf(vv * (1.f / 64.f) + 1e-5f);
    float l0 = fmaf(d0 * rs, s.foG1v[j0], s.foBe1v[j0]);
    float l1 = fmaf(d1 * rs, s.foG1v[j1], s.foBe1v[j1]);
    s.lnbuf[warp][j0] = l0;
    s.lnbuf[warp][j1] = l1;
    __syncwarp();

    a0 = s.foB1v[j0]; a1 = s.foB1v[j1];
    #pragma unroll 8
    for (int i = 0; i < 64; i++) {
        float xi = s.lnbuf[warp][i];
        a0 = fmaf(xi, s.FoW1[i][j0], a0);
        a1 = fmaf(xi, s.FoW1[i][j1], a1);
    }
    h0 += leaky(a0);
    h1 += leaky(a1);

    sm = h0 + h1;
    #pragma unroll
    for (int off = 16; off; off >>= 1) sm += __shfl_xor_sync(0xffffffffu, sm, off);
    m = sm * (1.f / 64.f);
    d0 = h0 - m; d1 = h1 - m;
    vv = fmaf(d0, d0, d1 * d1);
    #pragma unroll
    for (int off = 16; off; off >>= 1) vv += __shfl_xor_sync(0xffffffffu, vv, off);
    rs = rsqrtf(vv * (1.f / 64.f) + 1e-5f);
    l0 = fmaf(d0 * rs, s.foGfv[j0], s.foBefv[j0]);
    l1 = fmaf(d1 * rs, s.foGfv[j1], s.foBefv[j1]);

    float p0 = fmaf(l0, s.FoWf[j0][0], l1 * s.FoWf[j1][0]);
    float p1 = fmaf(l0, s.FoWf[j0][1], l1 * s.FoWf[j1][1]);
    #pragma unroll
    for (int off = 16; off; off >>= 1) {
        p0 += __shfl_xor_sync(0xffffffffu, p0, off);
        p1 += __shfl_xor_sync(0xffffffffu, p1, off);
    }
    if (lane == 0) {
        float lg0 = p0 + s.foBfv[0];
        float lg1 = p1 + s.foBfv[1];
        float mx = fmaxf(lg0, lg1);
        float e0 = expf(lg0 - mx);
        float e1 = expf(lg1 - mx);
        out[b * TP + tp] = e1 / (e0 + e1);
    }
}

extern "C" void kernel_launch(void* const* d_in, const int* in_sizes, int n_in,
                              void* d_out, int out_size)
{
    (void)in_sizes; (void)n_in; (void)out_size;
    const int*   skill = (const int*)  d_in[0];
    const int*   timeq = (const int*)  d_in[2];
    const int*   label = (const int*)  d_in[3];
    const float* adj   = (const float*)d_in[4];
    const float* nemb  = (const float*)d_in[5];
    const float* ivW0  = (const float*)d_in[6];
    const float* ivB0  = (const float*)d_in[7];
    const float* ivG1  = (const float*)d_in[8];
    const float* ivBe1 = (const float*)d_in[9];
    const float* ivW1  = (const float*)d_in[10];
    const float* ivB1  = (const float*)d_in[11];
    const float* ivGf  = (const float*)d_in[12];
    const float* ivBef = (const float*)d_in[13];
    const float* ivWf  = (const float*)d_in[14];
    const float* ivBf  = (const float*)d_in[15];
    const float* foW0  = (const float*)d_in[16];
    const float* foB0  = (const float*)d_in[17];
    const float* foG1  = (const float*)d_in[18];
    const float* foBe1 = (const float*)d_in[19];
    const float* foW1  = (const float*)d_in[20];
    const float* foB1  = (const float*)d_in[21];
    const float* foGf  = (const float*)d_in[22];
    const float* foBef = (const float*)d_in[23];
    const float* foWf  = (const float*)d_in[24];
    const float* foBf  = (const float*)d_in[25];

    cudaFuncSetAttribute(gtm_kernel, cudaFuncAttributeMaxDynamicSharedMemorySize,
                         (int)sizeof(Smem));

    dim3 grid((TP + WARPS - 1) / WARPS, BSZ);
    gtm_kernel<<<grid, 256, sizeof(Smem)>>>(
        skill, timeq, label, adj, nemb,
        ivW0, ivB0, ivG1, ivBe1, ivW1, ivB1, ivGf, ivBef, ivWf, ivBf,
        foW0, foB0, foG1, foBe1, foW1, foB1, foGf, foBef, foWf, foBf,
        (float*)d_out);
}